// round 1
// baseline (speedup 1.0000x reference)
#include <cuda_runtime.h>

// VQ-VAE quantization:
//   x   [32, 64, 64, 64] fp32  (B, C, H, W)
//   emb [1024, 64] fp32        (K, C)
// out (concatenated fp32): o [B,C,H,W] (8388608) | loss (1) | indices [B,H,W] (131072)
//
// o = emb[argmin_k ||z_n - e_k||^2] scattered back to BCHW (straight-through => o == e)
// loss = 1.25 * mean((x - e)^2)

#define NPOS      131072      // B*H*W
#define CDIM      64
#define KCODES    1024
#define HW        4096        // H*W
#define XSIZE     8388608     // B*C*H*W
#define CHUNK     128         // codes per smem chunk
#define THREADS   256
#define NBLOCKS   (NPOS / THREADS)   // 512

__device__ float g_e2[KCODES];
__device__ float g_partials[NBLOCKS];

// ---------------------------------------------------------------------------
// Pass 0: ||e_k||^2 per code
// ---------------------------------------------------------------------------
__global__ void e2_kernel(const float* __restrict__ emb) {
    int k = blockIdx.x * blockDim.x + threadIdx.x;
    if (k < KCODES) {
        const float4* row = reinterpret_cast<const float4*>(emb + k * CDIM);
        float s = 0.f;
#pragma unroll
        for (int i = 0; i < 16; i++) {
            float4 v = row[i];
            s += v.x * v.x + v.y * v.y + v.z * v.z + v.w * v.w;
        }
        g_e2[k] = s;
    }
}

// ---------------------------------------------------------------------------
// Pass 1: argmin + gather + o write + per-block loss partial
// ---------------------------------------------------------------------------
__global__ __launch_bounds__(THREADS, 2)
void vq_kernel(const float* __restrict__ x,
               const float* __restrict__ emb,
               float* __restrict__ out) {
    __shared__ float4 s_code[CHUNK * 16];   // 128 codes x 64 floats = 32 KB
    __shared__ float  s_e2[KCODES];         // 4 KB
    __shared__ float  s_red[THREADS];

    const int tid = threadIdx.x;
    const int n   = blockIdx.x * THREADS + tid;
    const int b   = n >> 12;          // n / HW
    const int hw  = n & (HW - 1);

    const float* xp = x + (size_t)b * CDIM * HW + hw;

    // z in registers (strided loads, coalesced across the warp per channel)
    float z[CDIM];
#pragma unroll
    for (int c = 0; c < CDIM; c++) z[c] = xp[c * HW];

    // preload all ||e||^2
    for (int i = tid; i < KCODES; i += THREADS) s_e2[i] = g_e2[i];

    float best = 3.4e38f;
    int   bidx = 0;

    for (int k0 = 0; k0 < KCODES; k0 += CHUNK) {
        __syncthreads();   // protect previous chunk readers (and e2 preload on iter 0)
        const float4* src = reinterpret_cast<const float4*>(emb + k0 * CDIM);
        for (int i = tid; i < CHUNK * 16; i += THREADS) s_code[i] = src[i];
        __syncthreads();

#pragma unroll 2
        for (int kk = 0; kk < CHUNK; kk++) {
            const float4* e = &s_code[kk * 16];
            float a0 = 0.f, a1 = 0.f, a2 = 0.f, a3 = 0.f;
#pragma unroll
            for (int i = 0; i < 16; i++) {
                float4 ev = e[i];   // broadcast LDS.128, conflict-free
                a0 = fmaf(z[4 * i + 0], ev.x, a0);
                a1 = fmaf(z[4 * i + 1], ev.y, a1);
                a2 = fmaf(z[4 * i + 2], ev.z, a2);
                a3 = fmaf(z[4 * i + 3], ev.w, a3);
            }
            float dot = (a0 + a1) + (a2 + a3);
            float d = s_e2[k0 + kk] - 2.0f * dot;   // ||z||^2 constant: irrelevant for argmin
            if (d < best) { best = d; bidx = k0 + kk; }   // strict < keeps first index on ties
        }
    }

    // gather chosen code, write o (== e), accumulate (x - e)^2
    const float4* erow = reinterpret_cast<const float4*>(emb + bidx * CDIM);
    float* op = out + (size_t)b * CDIM * HW + hw;
    float ls = 0.f;
#pragma unroll
    for (int i = 0; i < 16; i++) {
        float4 ev = __ldg(&erow[i]);
        op[(4 * i + 0) * HW] = ev.x;
        op[(4 * i + 1) * HW] = ev.y;
        op[(4 * i + 2) * HW] = ev.z;
        op[(4 * i + 3) * HW] = ev.w;
        float d0 = z[4 * i + 0] - ev.x;
        float d1 = z[4 * i + 1] - ev.y;
        float d2 = z[4 * i + 2] - ev.z;
        float d3 = z[4 * i + 3] - ev.w;
        ls = fmaf(d0, d0, ls);
        ls = fmaf(d1, d1, ls);
        ls = fmaf(d2, d2, ls);
        ls = fmaf(d3, d3, ls);
    }

    // indices (after o[XSIZE] and loss[1])
    out[XSIZE + 1 + n] = (float)bidx;

    // deterministic block reduction of loss partial
    s_red[tid] = ls;
    __syncthreads();
#pragma unroll
    for (int s = THREADS / 2; s > 0; s >>= 1) {
        if (tid < s) s_red[tid] += s_red[tid + s];
        __syncthreads();
    }
    if (tid == 0) g_partials[blockIdx.x] = s_red[0];
}

// ---------------------------------------------------------------------------
// Pass 2: loss finalize (deterministic fixed-tree, double accumulation)
// ---------------------------------------------------------------------------
__global__ void finalize_kernel(float* __restrict__ out) {
    __shared__ double sd[NBLOCKS];
    int t = threadIdx.x;
    sd[t] = (double)g_partials[t];
    __syncthreads();
#pragma unroll
    for (int s = NBLOCKS / 2; s > 0; s >>= 1) {
        if (t < s) sd[t] += sd[t + s];
        __syncthreads();
    }
    if (t == 0) {
        // loss = codebook + BETA*commitment = (1 + 0.25) * mean((x-e)^2)
        out[XSIZE] = (float)(1.25 * sd[0] / (double)XSIZE);
    }
}

// ---------------------------------------------------------------------------
extern "C" void kernel_launch(void* const* d_in, const int* in_sizes, int n_in,
                              void* d_out, int out_size) {
    const float* x   = (const float*)d_in[0];
    const float* emb = (const float*)d_in[1];
    // defensive: metadata order is (x, emb); swap if sizes indicate otherwise
    if (n_in >= 2 && in_sizes[0] == KCODES * CDIM && in_sizes[1] == XSIZE) {
        const float* t = x; x = emb; emb = t;
    }
    float* out = (float*)d_out;

    e2_kernel<<<(KCODES + 255) / 256, 256>>>(emb);
    vq_kernel<<<NBLOCKS, THREADS>>>(x, emb, out);
    finalize_kernel<<<1, NBLOCKS>>>(out);
}